// round 1
// baseline (speedup 1.0000x reference)
#include <cuda_runtime.h>
#include <math.h>

// ChunkRanker: per-chunk std-based "realism" + cosine-boundary score.
// chunks: [N, 128, 64] f32 (N=4096), regime_probs: [9] (unused, consistency=0.5),
// previous_context: [128, 64] f32. out: [N] f32.
//
// out[n] = realism(std(chunks[n], ddof=1)) + 0.15 + 0.2 * cos(chunks[n,:10,:], ctx[-10:,:])

#define THREADS      256
#define CHUNK_ELEMS  8192          // 128*64
#define VEC          (CHUNK_ELEMS / 4)   // 2048 float4
#define START_ELEMS  640           // first 10 rows * 64
#define START_VEC    (START_ELEMS / 4)   // 160 float4
#define EPS          1e-8f

__global__ __launch_bounds__(THREADS)
void chunk_ranker_kernel(const float* __restrict__ chunks,
                         const float* __restrict__ prev_ctx,  // already offset to last 10 rows
                         float* __restrict__ out,
                         int n_chunks)
{
    __shared__ float4 ctx_sh[START_VEC];
    __shared__ float  red[8][4];

    const int n   = blockIdx.x;
    const int tid = threadIdx.x;
    if (n >= n_chunks) return;

    // Stage ctx tail (640 floats = 160 float4) into shared. L2-resident after wave 1.
    if (tid < START_VEC) {
        ctx_sh[tid] = reinterpret_cast<const float4*>(prev_ctx)[tid];
    }
    __syncthreads();

    const float4* base =
        reinterpret_cast<const float4*>(chunks) + (size_t)n * VEC;

    float sum = 0.f, sq = 0.f, dot = 0.f, ssq = 0.f;

    // Exactly 8 iterations: front-batched float4 LDGs (MLP=8).
    #pragma unroll
    for (int it = 0; it < VEC / THREADS; ++it) {
        const int i = tid + it * THREADS;
        const float4 v = base[i];
        sum += v.x + v.y + v.z + v.w;
        sq  += v.x * v.x + v.y * v.y + v.z * v.z + v.w * v.w;
        // Only the first iteration can hit the "start" region (i < 160 < 256).
        if (i < START_VEC) {
            const float4 c = ctx_sh[i];
            dot += v.x * c.x + v.y * c.y + v.z * c.z + v.w * c.w;
            ssq += v.x * v.x + v.y * v.y + v.z * v.z + v.w * v.w;
        }
    }

    // Warp reduction of all four accumulators.
    #pragma unroll
    for (int o = 16; o > 0; o >>= 1) {
        sum += __shfl_down_sync(0xffffffffu, sum, o);
        sq  += __shfl_down_sync(0xffffffffu, sq,  o);
        dot += __shfl_down_sync(0xffffffffu, dot, o);
        ssq += __shfl_down_sync(0xffffffffu, ssq, o);
    }
    const int w = tid >> 5, l = tid & 31;
    if (l == 0) {
        red[w][0] = sum; red[w][1] = sq; red[w][2] = dot; red[w][3] = ssq;
    }
    __syncthreads();

    if (tid == 0) {
        float S = 0.f, Q = 0.f, D = 0.f, SS = 0.f;
        #pragma unroll
        for (int i = 0; i < THREADS / 32; ++i) {
            S += red[i][0]; Q += red[i][1]; D += red[i][2]; SS += red[i][3];
        }

        const float N   = (float)CHUNK_ELEMS;
        const float var = (Q - S * S / N) / (N - 1.0f);
        const float sd  = sqrtf(fmaxf(var, 0.0f));

        float realism;
        if (sd < 0.01f)      realism = sd * 10.0f;
        else if (sd > 0.5f)  realism = 0.5f / sd;
        else                 realism = 1.0f - fabsf(sd - 0.1f);

        // ctx norm^2 (identical across blocks; 160-iter smem loop, negligible).
        float cs = 0.f;
        #pragma unroll 8
        for (int i = 0; i < START_VEC; ++i) {
            const float4 c = ctx_sh[i];
            cs += c.x * c.x + c.y * c.y + c.z * c.z + c.w * c.w;
        }

        const float denom    = fmaxf(sqrtf(SS) * sqrtf(cs), EPS);
        const float boundary = D / denom;

        out[n] = realism + 0.3f * 0.5f + 0.2f * boundary;
    }
}

extern "C" void kernel_launch(void* const* d_in, const int* in_sizes, int n_in,
                              void* d_out, int out_size)
{
    const float* chunks   = (const float*)d_in[0];
    // d_in[1] = regime_probs, unused (regime_consistency is a constant 0.5)
    const float* prev_ctx = (const float*)d_in[2];

    const int n_chunks = in_sizes[0] / CHUNK_ELEMS;           // 4096
    const int ctx_off  = in_sizes[2] - START_ELEMS;           // last 10 rows of [128,64]

    float* out = (float*)d_out;

    chunk_ranker_kernel<<<n_chunks, THREADS>>>(chunks, prev_ctx + ctx_off, out, n_chunks);
}

// round 2
// speedup vs baseline: 1.1635x; 1.1635x over previous
#include <cuda_runtime.h>
#include <math.h>

// ChunkRanker: per-chunk std-based "realism" + cosine-boundary score.
// chunks: [4096, 128, 64] f32, regime_probs: [9] (unused), previous_context: [128, 64] f32.
// out[n] = realism(std(chunks[n], ddof=1)) + 0.15 + 0.2 * cos(chunks[n,:10,:], ctx[-10:,:])

#define THREADS      256
#define CHUNK_ELEMS  8192               // 128*64
#define VEC          (CHUNK_ELEMS / 4)  // 2048 float4
#define ITERS        (VEC / THREADS)    // 8
#define START_VEC    160                // first 10 rows * 64 floats / 4
#define EPS          1e-8f

__global__ __launch_bounds__(THREADS, 4)
void chunk_ranker_kernel(const float* __restrict__ chunks,
                         const float* __restrict__ prev_ctx,  // offset to last 10 rows
                         float* __restrict__ out,
                         int n_chunks)
{
    __shared__ float red[8][5];

    const int n   = blockIdx.x;
    const int tid = threadIdx.x;
    if (n >= n_chunks) return;

    const float4* base = reinterpret_cast<const float4*>(chunks) + (size_t)n * VEC;

    // Front-batch ALL chunk loads (MLP=8) before any other memory traffic.
    float4 v[ITERS];
    #pragma unroll
    for (int it = 0; it < ITERS; ++it)
        v[it] = base[tid + it * THREADS];

    // ctx element for this thread (L2-resident after wave 1; no smem, no barrier).
    float4 c = make_float4(0.f, 0.f, 0.f, 0.f);
    if (tid < START_VEC)
        c = reinterpret_cast<const float4*>(prev_ctx)[tid];

    float sum = 0.f, sq = 0.f;
    #pragma unroll
    for (int it = 0; it < ITERS; ++it) {
        sum += v[it].x + v[it].y + v[it].z + v[it].w;
        sq  += v[it].x * v[it].x + v[it].y * v[it].y
             + v[it].z * v[it].z + v[it].w * v[it].w;
    }

    // Boundary terms: only iteration 0 covers elements [0,640).
    float dot = 0.f, ssq = 0.f, csq = 0.f;
    if (tid < START_VEC) {
        const float4 a = v[0];
        dot = a.x * c.x + a.y * c.y + a.z * c.z + a.w * c.w;
        ssq = a.x * a.x + a.y * a.y + a.z * a.z + a.w * a.w;
        csq = c.x * c.x + c.y * c.y + c.z * c.z + c.w * c.w;
    }

    // Warp reduction of 5 accumulators.
    #pragma unroll
    for (int o = 16; o > 0; o >>= 1) {
        sum += __shfl_down_sync(0xffffffffu, sum, o);
        sq  += __shfl_down_sync(0xffffffffu, sq,  o);
        dot += __shfl_down_sync(0xffffffffu, dot, o);
        ssq += __shfl_down_sync(0xffffffffu, ssq, o);
        csq += __shfl_down_sync(0xffffffffu, csq, o);
    }
    const int w = tid >> 5, l = tid & 31;
    if (l == 0) {
        red[w][0] = sum; red[w][1] = sq; red[w][2] = dot;
        red[w][3] = ssq; red[w][4] = csq;
    }
    __syncthreads();

    // Warp 0 reduces the 8 per-warp partials with shuffles (no serial loop).
    if (tid < 32) {
        float s0 = (tid < 8) ? red[tid][0] : 0.f;
        float s1 = (tid < 8) ? red[tid][1] : 0.f;
        float s2 = (tid < 8) ? red[tid][2] : 0.f;
        float s3 = (tid < 8) ? red[tid][3] : 0.f;
        float s4 = (tid < 8) ? red[tid][4] : 0.f;
        #pragma unroll
        for (int o = 4; o > 0; o >>= 1) {
            s0 += __shfl_down_sync(0xffffffffu, s0, o);
            s1 += __shfl_down_sync(0xffffffffu, s1, o);
            s2 += __shfl_down_sync(0xffffffffu, s2, o);
            s3 += __shfl_down_sync(0xffffffffu, s3, o);
            s4 += __shfl_down_sync(0xffffffffu, s4, o);
        }
        if (tid == 0) {
            const float N   = (float)CHUNK_ELEMS;
            const float var = (s1 - s0 * s0 / N) / (N - 1.0f);
            const float sd  = sqrtf(fmaxf(var, 0.0f));

            float realism;
            if (sd < 0.01f)      realism = sd * 10.0f;
            else if (sd > 0.5f)  realism = 0.5f / sd;
            else                 realism = 1.0f - fabsf(sd - 0.1f);

            const float denom    = fmaxf(sqrtf(s3) * sqrtf(s4), EPS);
            const float boundary = s2 / denom;

            out[n] = realism + 0.3f * 0.5f + 0.2f * boundary;
        }
    }
}

extern "C" void kernel_launch(void* const* d_in, const int* in_sizes, int n_in,
                              void* d_out, int out_size)
{
    const float* chunks   = (const float*)d_in[0];
    // d_in[1] = regime_probs, unused (regime_consistency is the constant 0.5)
    const float* prev_ctx = (const float*)d_in[2];

    const int n_chunks = in_sizes[0] / CHUNK_ELEMS;   // 4096
    const int ctx_off  = in_sizes[2] - START_VEC * 4; // last 10 rows of [128,64]

    float* out = (float*)d_out;

    chunk_ranker_kernel<<<n_chunks, THREADS>>>(chunks, prev_ctx + ctx_off, out, n_chunks);
}